// round 13
// baseline (speedup 1.0000x reference)
#include <cuda_runtime.h>
#include <cuda_fp16.h>
#include <cstdint>

#define SEQ 32
#define EDIM 256
#define HDIM 256
#define GDIM 1024
#define ROWS 32
#define NCTAS 128
#define NTHREADS 512
#define NWARPS 16
#define NPIN 6    // kc slices pinned in smem (of 32)

#define XSW 132   // half2 words per row (264 halves): conflict-free
#define XS_WORDS (ROWS*XSW)                     // 4224 words
#define WPIN_WORD_OFF (2*XS_WORDS)              // Xs + single H buffer
#define WPIN_UINT4 (NWARPS*NPIN*4*32)           // 12288 uint4 = 196,608 B
#define SMEM_BYTES (WPIN_WORD_OFF*4 + WPIN_UINT4*16)   // 230,400 B <= 232,448

// fp16 B-fragment packed weights, uint4 pairs (nf 2j, 2j+1):
// index = ((w*32 + kc)*4 + j)*32 + lane ; w = warp 0..15 (64-col slice),
// kc 0..15 = X part (W_ih), 16..31 = H part (W_hh)
__device__ __align__(16) uint4 g_wpk4[NWARPS*32*4*32];
__device__ float g_bperm[GDIM];   // permuted bias (b_ih + b_hh)

__device__ __forceinline__ uint32_t f2h2(float lo, float hi) {
    __half2 p = __floats2half2_rn(lo, hi);
    return *(uint32_t*)&p;
}
__device__ __forceinline__ float tanh_fast(float x) {
    float r; asm("tanh.approx.f32 %0, %1;" : "=f"(r) : "f"(x)); return r;
}
__device__ __forceinline__ float sigmoid_fast(float x) {
    return fmaf(0.5f, tanh_fast(0.5f * x), 0.5f);
}

#define MMA_F16(d, a, b0, b1)                                               \
    asm volatile("mma.sync.aligned.m16n8k16.row.col.f32.f16.f16.f32 "      \
                 "{%0,%1,%2,%3}, {%4,%5,%6,%7}, {%8,%9}, {%0,%1,%2,%3};"    \
                 : "+f"((d)[0]), "+f"((d)[1]), "+f"((d)[2]), "+f"((d)[3])   \
                 : "r"((a)[0]), "r"((a)[1]), "r"((a)[2]), "r"((a)[3]),      \
                   "r"(b0), "r"(b1))

// =================== prep: permute + fp16 + fragment-pack ===================
__global__ void prep_kernel(const float* __restrict__ wih,
                            const float* __restrict__ whh,
                            const float* __restrict__ bih,
                            const float* __restrict__ bhh) {
    int i = blockIdx.x * blockDim.x + threadIdx.x;   // 0..65535
    if (i >= NWARPS*32*4*32) return;
    int lane = i & 31;
    int j    = (i >> 5) & 3;
    int kc   = (i >> 7) & 31;
    int w    = (i >> 12) & 15;
    int grp  = lane >> 2;
    int tg   = lane & 3;

    const float* W = (kc < 16) ? wih : whh;
    int kbase = (kc & 15)*16;

    uint4 v;
    #pragma unroll
    for (int h = 0; h < 2; ++h) {
        int nf = 2*j + h;
        int colperm = w*64 + nf*8 + grp;
        int unit = colperm >> 2, gate = colperm & 3;
        const float* wr = W + (gate*256 + unit)*256 + kbase;
        uint32_t b0 = f2h2(wr[2*tg], wr[2*tg + 1]);
        uint32_t b1 = f2h2(wr[2*tg + 8], wr[2*tg + 9]);
        if (h == 0) { v.x = b0; v.y = b1; } else { v.z = b0; v.w = b1; }
    }
    g_wpk4[i] = v;

    if (i < GDIM) {
        int u2 = i >> 2, g2 = i & 3;
        g_bperm[i] = bih[g2*256 + u2] + bhh[g2*256 + u2];
    }
}

// =================== fused LSTM kernel (fp16 MMA, smem-pinned weight slice) ===================
__global__ __launch_bounds__(NTHREADS, 1)
void lstm_fused_kernel(const float* __restrict__ x, float* __restrict__ out) {
    extern __shared__ uint32_t sm[];           // half2 words
    uint32_t* Xs = sm;                          // [32][XSW]
    uint32_t* Hb = sm + XS_WORDS;               // single h buffer [32][XSW]
    uint4*    Wp = (uint4*)(sm + WPIN_WORD_OFF);// pinned weights [w][kc<NPIN][j][lane]

    const int tid  = threadIdx.x;
    const int lane = tid & 31;
    const int w    = tid >> 5;                  // 0..15, owns gate cols w*64..+63
    const int grp  = lane >> 2;
    const int tg   = lane & 3;
    const int tgl  = tg & 1;
    const int tgh  = tg >> 1;
    const long rowbase = (long)blockIdx.x * ROWS;

    // zero h buffer; fill pinned weight slice (coalesced)
    for (int i = tid; i < XS_WORDS; i += NTHREADS) Hb[i] = 0u;
    for (int idx = tid; idx < WPIN_UINT4; idx += NTHREADS) {
        int w2 = idx / (NPIN*4*32);
        int r  = idx % (NPIN*4*32);            // kc*128 + j*32 + lane
        Wp[idx] = g_wpk4[w2*4096 + r];
    }
    __syncthreads();

    float cst[2][8];
    #pragma unroll
    for (int a = 0; a < 2; ++a)
        #pragma unroll
        for (int b = 0; b < 8; ++b) cst[a][b] = 0.0f;

    const float* xbase = x + rowbase * (SEQ*EDIM);
    const uint4* wbase = g_wpk4 + ((size_t)w*32*4)*32 + lane;
    const uint4* wpin  = Wp + ((size_t)w*NPIN*4)*32 + lane;

    for (int s = 0; s < SEQ; ++s) {
        // ---- stage x_s tile [32][256] as fp16 half2 ----
        {
            const long srow = (long)s * EDIM;
            #pragma unroll
            for (int it = 0; it < 4; ++it) {
                int fi = tid + it * NTHREADS;
                int r  = fi >> 6;
                int cq = fi & 63;
                const float4 v = *((const float4*)(xbase + (long)r*(SEQ*EDIM) + srow) + cq);
                Xs[r*XSW + cq*2]     = f2h2(v.x, v.y);
                Xs[r*XSW + cq*2 + 1] = f2h2(v.z, v.w);
            }
        }
        __syncthreads();

        const int nkc = (s == 0) ? 16 : 32;     // s=0: h=0, skip H part

        // accumulators, bias-initialized
        float d[2][8][4];
        #pragma unroll
        for (int nf = 0; nf < 8; ++nf) {
            int col = w*64 + nf*8 + 2*tg;
            float b0v = g_bperm[col], b1v = g_bperm[col + 1];
            d[0][nf][0] = b0v; d[0][nf][1] = b1v; d[0][nf][2] = b0v; d[0][nf][3] = b1v;
            d[1][nf][0] = b0v; d[1][nf][1] = b1v; d[1][nf][2] = b0v; d[1][nf][3] = b1v;
        }

        // ---- merged X+H mainloop, 2-slot software pipeline ----
        uint4   wb[2][4];
        uint32_t ab[2][8];
        // prologue: kc=0 (pinned)
        {
            #pragma unroll
            for (int j = 0; j < 4; ++j) wb[0][j] = wpin[j*32];
            #pragma unroll
            for (int mh = 0; mh < 2; ++mh) {
                int r0 = mh*16 + grp;
                ab[0][mh*4+0] = Xs[r0*XSW + tg];
                ab[0][mh*4+1] = Xs[(r0+8)*XSW + tg];
                ab[0][mh*4+2] = Xs[r0*XSW + 4 + tg];
                ab[0][mh*4+3] = Xs[(r0+8)*XSW + 4 + tg];
            }
        }

        #pragma unroll 2
        for (int kc = 0; kc < nkc; ++kc) {
            const int cur = kc & 1, nxt = cur ^ 1;
            if (kc + 1 < nkc) {
                if (kc + 1 < NPIN) {
                    const uint4* bp = wpin + (size_t)(kc + 1)*4*32;
                    #pragma unroll
                    for (int j = 0; j < 4; ++j) wb[nxt][j] = bp[j*32];
                } else {
                    const uint4* bp = wbase + (size_t)(kc + 1)*4*32;
                    #pragma unroll
                    for (int j = 0; j < 4; ++j) wb[nxt][j] = bp[j*32];
                }
                const uint32_t* A = (kc + 1 < 16) ? Xs : Hb;
                const int kw = ((kc + 1) & 15)*8;
                #pragma unroll
                for (int mh = 0; mh < 2; ++mh) {
                    int r0 = mh*16 + grp;
                    ab[nxt][mh*4+0] = A[r0*XSW + kw + tg];
                    ab[nxt][mh*4+1] = A[(r0+8)*XSW + kw + tg];
                    ab[nxt][mh*4+2] = A[r0*XSW + kw + 4 + tg];
                    ab[nxt][mh*4+3] = A[(r0+8)*XSW + kw + 4 + tg];
                }
            }
            #pragma unroll
            for (int j = 0; j < 4; ++j) {
                uint4 b = wb[cur][j];
                MMA_F16(d[0][2*j],   &ab[cur][0], b.x, b.y);
                MMA_F16(d[1][2*j],   &ab[cur][4], b.x, b.y);
                MMA_F16(d[0][2*j+1], &ab[cur][0], b.z, b.w);
                MMA_F16(d[1][2*j+1], &ab[cur][4], b.z, b.w);
            }
        }

        __syncthreads();   // all H reads done before overwriting Hb

        // ---- activation in registers (tanh.approx) ----
        __half* Hnxt = (__half*)Hb;
        #pragma unroll
        for (int mh = 0; mh < 2; ++mh) {
            #pragma unroll
            for (int nf = 0; nf < 8; ++nf) {
                float c0 = d[mh][nf][0], c1 = d[mh][nf][1];
                float c2 = d[mh][nf][2], c3 = d[mh][nf][3];
                float x0 = __shfl_xor_sync(0xffffffffu, tgl ? c0 : c2, 1);
                float x1 = __shfl_xor_sync(0xffffffffu, tgl ? c1 : c3, 1);
                float gi = tgl ? x0 : c0;
                float gf = tgl ? x1 : c1;
                float gg = tgl ? c2 : x0;
                float go = tgl ? c3 : x1;
                int row = grp + 8*tgl + 16*mh;
                int u   = w*16 + 2*nf + tgh;        // global unit 0..255
                float cv = sigmoid_fast(gf) * cst[mh][nf]
                         + sigmoid_fast(gi) * tanh_fast(gg);
                cst[mh][nf] = cv;
                float h = sigmoid_fast(go) * tanh_fast(cv);
                Hnxt[row*(2*XSW) + u] = __float2half_rn(h);
                if (s == SEQ - 1) out[(rowbase + row)*HDIM + u] = h;
            }
        }
        __syncthreads();
    }
}

extern "C" void kernel_launch(void* const* d_in, const int* in_sizes, int n_in,
                              void* d_out, int out_size) {
    const float* x   = (const float*)d_in[0];
    const float* wih = (const float*)d_in[1];
    const float* whh = (const float*)d_in[2];
    const float* bih = (const float*)d_in[3];
    const float* bhh = (const float*)d_in[4];
    float* out = (float*)d_out;

    cudaFuncSetAttribute(lstm_fused_kernel,
                         cudaFuncAttributeMaxDynamicSharedMemorySize, SMEM_BYTES);

    prep_kernel<<<(NWARPS*32*4*32 + 255)/256, 256>>>(wih, whh, bih, bhh);
    lstm_fused_kernel<<<NCTAS, NTHREADS, SMEM_BYTES>>>(x, out);
}